// round 13
// baseline (speedup 1.0000x reference)
#include <cuda_runtime.h>
#include <cstdint>

// Problem constants
#define B_       512
#define P_       65536
#define NOUT_    512
#define COUT_    4
#define NCLS_    10

// Decomposition: grid 148 = 4 row-groups (128 rows) x 37 px-groups, 1 block/SM.
// Tile = 128 px (512 B/row). Staging now uses cp.async.bulk (one 512B bulk per
// row, 129 instrs/tile, warp 0 only) + mbarrier complete_tx — R12 showed the
// 4096 per-tile LDGSTS were the pace-setter (DRAM stuck at 3.3 TB/s).
#define RGS      4
#define RROWS    128
#define PGS      37
#define GRIDM    (RGS * PGS)          // 148
#define TILE_P   128
#define TILES_RG 512
#define XSTR     132                  // floats per smem row (pad 4: conflict-free LDS.128)
#define WPAD     12
#define DEPTH    3
#define TX_BYTES (RROWS * TILE_P * 4 + TILE_P * 4)   // x tile + seg tile = 66048

#define XBUF_FLOATS (RROWS * XSTR)                     // 16896
#define XS_BYTES    (DEPTH * XBUF_FLOATS * 4)          // 202752
#define WSM_BYTES   (NOUT_ * WPAD * 4)                 // 24576
#define SEGB_BYTES  (DEPTH * TILE_P * 4)               // 1536
#define BRED_BYTES  704                                // 16x10 warp beff + bsm
#define MBAR_BYTES  64                                 // 3 mbarriers (+pad)
#define SMEM_TOTAL  (XS_BYTES + WSM_BYTES + SEGB_BYTES + BRED_BYTES + MBAR_BYTES) // 229632

// Scratch (allocation-free)
__device__ float g_partial[PGS * B_ * NCLS_];   // [37][512][10]
__device__ int   g_cnt[RGS];                    // arrival counters (reset by finalizer)

__device__ __forceinline__ uint32_t smem_u32(const void* p) {
    return (uint32_t)__cvta_generic_to_shared(p);
}
__device__ __forceinline__ unsigned long long packf2(float v) {
    unsigned long long r;
    asm("mov.b64 %0, {%1, %1};" : "=l"(r) : "f"(v));
    return r;
}
#define FMA2(acc, xv, wv) \
    asm("fma.rn.f32x2 %0, %1, %2, %0;" : "+l"(acc) : "l"(xv), "l"(wv))

#define MBAR_INIT(addr, cnt) \
    asm volatile("mbarrier.init.shared.b64 [%0], %1;" :: "r"(addr), "r"(cnt) : "memory")
#define MBAR_EXPECT_TX(addr, tx) \
    asm volatile("mbarrier.arrive.expect_tx.shared.b64 _, [%0], %1;" :: "r"(addr), "r"(tx) : "memory")
#define MBAR_WAIT(addr, ph) do {                                                  \
    asm volatile(                                                                 \
        "{\n\t.reg .pred P1;\n\t"                                                 \
        "WAIT_%=:\n\t"                                                            \
        "mbarrier.try_wait.parity.acquire.cta.shared::cta.b64 P1, [%0], %1, 0x989680;\n\t" \
        "@P1 bra.uni DONE_%=;\n\t"                                                \
        "bra.uni WAIT_%=;\n\t"                                                    \
        "DONE_%=:\n\t}"                                                           \
        :: "r"(addr), "r"(ph) : "memory");                                        \
} while (0)
#define BULK_G2S(smem, gmem, bytes, mbar) \
    asm volatile("cp.async.bulk.shared::cta.global.mbarrier::complete_tx::bytes " \
                 "[%0], [%1], %2, [%3];"                                          \
                 :: "r"(smem), "l"(gmem), "r"(bytes), "r"(mbar) : "memory")

// ---------------------------------------------------------------------------
__global__ void __launch_bounds__(512, 1)
fused_main_k(const float* __restrict__ x, const int* __restrict__ seg,
             const float* __restrict__ W_fgl, const float* __restrict__ b_fgl,
             const float* __restrict__ W_fc, const float* __restrict__ b_fc,
             float* __restrict__ out) {
    extern __shared__ __align__(16) char dynsmem[];
    float* xs   = (float*)dynsmem;                                    // [3][16896]
    float* wsm  = (float*)(dynsmem + XS_BYTES);                       // [512*12]
    int*   segb = (int*)(dynsmem + XS_BYTES + WSM_BYTES);             // [3][128]
    float* bred = (float*)(dynsmem + XS_BYTES + WSM_BYTES + SEGB_BYTES); // [16][10]
    float* bsm  = bred + 16 * NCLS_;                                  // [10]
    const uint32_t mbar0 =
        smem_u32(dynsmem + XS_BYTES + WSM_BYTES + SEGB_BYTES + BRED_BYTES);

    const int t    = threadIdx.x;
    const int warp = t >> 5;
    const int lane = t & 31;
    const int g    = blockIdx.x / PGS;      // row-group (0..3)
    const int pg   = blockIdx.x % PGS;      // px-group  (0..36)
    const int tStart = (pg * TILES_RG) / PGS;
    const int nT     = ((pg + 1) * TILES_RG) / PGS - tStart;   // 13 or 14

    const float* xbase = x + (size_t)(g * RROWS) * P_;

    // mbarrier init (one arrival per phase: the expect_tx arrive).
    if (t == 0) {
#pragma unroll
        for (int i = 0; i < DEPTH; i++) MBAR_INIT(mbar0 + i * 8, 1);
        asm volatile("fence.proxy.async.shared::cta;" ::: "memory");
    }
    __syncthreads();

    // warp-0-only bulk staging of tile ft into buf ft%3.
    auto stage = [&](int ft) {
        int buf  = ft % DEPTH;
        uint32_t mb = mbar0 + buf * 8;
        int pOff = (tStart + ft) * TILE_P;
        uint32_t xsb = smem_u32(xs + buf * XBUF_FLOATS);
        if (lane == 0) MBAR_EXPECT_TX(mb, TX_BYTES);
#pragma unroll
        for (int i = 0; i < 4; i++) {
            int row = lane + i * 32;
            BULK_G2S(xsb + (uint32_t)(row * XSTR) * 4,
                     xbase + (size_t)row * P_ + pOff, TILE_P * 4, mb);
        }
        if (lane == 0)
            BULK_G2S(smem_u32(segb + buf * TILE_P), seg + pOff, TILE_P * 4, mb);
    };

    // Prologue: 2 tiles in flight, then Weff + beff (overlapped with bulk DMA).
    if (warp == 0) { stage(0); stage(1); }
    {
        int j = t;                              // 512 threads == 512 regions
        float w[NCLS_], locb[NCLS_];
#pragma unroll
        for (int k = 0; k < NCLS_; k++) { w[k] = 0.f; locb[k] = 0.f; }
#pragma unroll
        for (int c = 0; c < COUT_; c++) {
            int r = c * NOUT_ + j;
            float a  = W_fgl[r];
            float bb = b_fgl[r];
            const float* wf = W_fc + r * NCLS_;
#pragma unroll
            for (int k = 0; k < NCLS_; k++) {
                float wv = wf[k];
                w[k]    += a * wv;
                locb[k] += bb * wv;
            }
        }
#pragma unroll
        for (int k = 0; k < NCLS_; k++) wsm[j * WPAD + k] = w[k];
#pragma unroll
        for (int off = 16; off >= 1; off >>= 1)
#pragma unroll
            for (int k = 0; k < NCLS_; k++)
                locb[k] += __shfl_xor_sync(0xffffffffu, locb[k], off);
        if (lane == 0)
#pragma unroll
            for (int k = 0; k < NCLS_; k++) bred[warp * NCLS_ + k] = locb[k];
    }
    // (iteration 0's __syncthreads orders wsm/bred before any reads)

    unsigned long long acc[4][5];   // [row-set][class-pair] f32x2
#pragma unroll
    for (int rs = 0; rs < 4; rs++)
#pragma unroll
        for (int q = 0; q < 5; q++) acc[rs][q] = 0ull;

    auto compute = [&](int buf) {
        // warp handles px [warp*8, warp*8+8); lane rows: lane,+32,+64,+96
        const float* xb = &xs[buf * XBUF_FLOATS + lane * XSTR + warp * 8];
        int4 s0 = *(const int4*)&segb[buf * TILE_P + warp * 8];       // broadcast
        int4 s1 = *(const int4*)&segb[buf * TILE_P + warp * 8 + 4];
#pragma unroll
        for (int h = 0; h < 2; h++) {
            float4 xr[4];
#pragma unroll
            for (int rs = 0; rs < 4; rs++)
                xr[rs] = *(const float4*)(xb + rs * 32 * XSTR + h * 4);
            int4 sid = h ? s1 : s0;
#pragma unroll
            for (int j = 0; j < 4; j++) {
                int id = (j == 0) ? sid.x : (j == 1) ? sid.y : (j == 2) ? sid.z : sid.w;
                const unsigned long long* wrow =
                    (const unsigned long long*)&wsm[id * WPAD];
                ulonglong2 wab = *(const ulonglong2*)(wrow);      // k0..3 (broadcast)
                ulonglong2 wcd = *(const ulonglong2*)(wrow + 2);  // k4..7
                unsigned long long we = wrow[4];                   // k8..9
#pragma unroll
                for (int rs = 0; rs < 4; rs++) {
                    float xv = (j == 0) ? xr[rs].x : (j == 1) ? xr[rs].y
                             : (j == 2) ? xr[rs].z : xr[rs].w;
                    unsigned long long xp = packf2(xv);
                    FMA2(acc[rs][0], xp, wab.x);
                    FMA2(acc[rs][1], xp, wab.y);
                    FMA2(acc[rs][2], xp, wcd.x);
                    FMA2(acc[rs][3], xp, wcd.y);
                    FMA2(acc[rs][4], xp, we);
                }
            }
        }
    };

#pragma unroll 1
    for (int ft = 0; ft < nT; ft++) {
        int buf = ft % DEPTH;
        MBAR_WAIT(mbar0 + buf * 8, (ft / DEPTH) & 1);   // tile ft arrived
        __syncthreads();                                 // compute(ft-1) done everywhere
        if (ft + 2 < nT && warp == 0) stage(ft + 2);     // refill buf (ft-1)%3
        compute(buf);
    }
    __syncthreads();   // all computes done; xs reusable as reduction space

    // Epilogue: reduce 16 warps' partials -> one block partial (fixed order).
    float* red = xs;                                     // 10240 floats used
#pragma unroll
    for (int rs = 0; rs < 4; rs++) {
        int row = lane + rs * 32;
        if (warp < 8) {
#pragma unroll
            for (int q = 0; q < 5; q++) {
                float lo, hi;
                asm("mov.b64 {%0,%1}, %2;" : "=f"(lo), "=f"(hi) : "l"(acc[rs][q]));
                red[(warp * RROWS + row) * NCLS_ + 2 * q]     = lo;
                red[(warp * RROWS + row) * NCLS_ + 2 * q + 1] = hi;
            }
        }
    }
    __syncthreads();
    if (warp >= 8) {
#pragma unroll
        for (int rs = 0; rs < 4; rs++) {
            int row = lane + rs * 32;
            float* dst = &red[((warp - 8) * RROWS + row) * NCLS_];
#pragma unroll
            for (int q = 0; q < 5; q++) {
                float lo, hi;
                asm("mov.b64 {%0,%1}, %2;" : "=f"(lo), "=f"(hi) : "l"(acc[rs][q]));
                dst[2 * q]     += lo;
                dst[2 * q + 1] += hi;
            }
        }
    }
    __syncthreads();
#pragma unroll
    for (int off = 4; off >= 1; off >>= 1) {
        for (int i = t; i < off * RROWS * NCLS_; i += 512) {
            int slot = i / (RROWS * NCLS_);
            int rem  = i - slot * (RROWS * NCLS_);
            red[slot * RROWS * NCLS_ + rem] += red[(slot + off) * RROWS * NCLS_ + rem];
        }
        __syncthreads();
    }
    if (t < NCLS_) {            // bsm: 16 warp beff partials + b_fc (fixed order)
        float a0 = 0.f, a1 = 0.f;
#pragma unroll
        for (int i = 0; i < 16; i += 2) {
            a0 += bred[i * NCLS_ + t];
            a1 += bred[(i + 1) * NCLS_ + t];
        }
        bsm[t] = b_fc[t] + a0 + a1;
    }
    for (int i = t; i < RROWS * NCLS_; i += 512) {   // 1280 entries
        g_partial[((size_t)pg * B_ + g * RROWS) * NCLS_ + i] = red[i];
    }
    __syncthreads();

    // Last block of this row-group finalizes (threadFenceReduction pattern).
    __shared__ int is_last;
    if (t == 0) {
        __threadfence();
        int old = atomicAdd(&g_cnt[g], 1);
        is_last = (old == PGS - 1);
    }
    __syncthreads();
    if (is_last) {
        __threadfence();   // acquire all 37 partials
        for (int i = t; i < RROWS * NCLS_; i += 512) {
            int n = g * RROWS + i / NCLS_;
            int k = i % NCLS_;
            float sum = bsm[k];
#pragma unroll
            for (int s = 0; s < PGS; s++)      // fixed order: deterministic
                sum += g_partial[((size_t)s * B_ + n) * NCLS_ + k];
            out[n * NCLS_ + k] = sum;
        }
        __syncthreads();
        if (t == 0) g_cnt[g] = 0;              // reset for next (graph) launch
    }
}

// ---------------------------------------------------------------------------
extern "C" void kernel_launch(void* const* d_in, const int* in_sizes, int n_in,
                              void* d_out, int out_size) {
    const float* x     = (const float*)d_in[0];   // [512, 65536]
    const float* W_fgl = (const float*)d_in[1];   // [4, 512]
    const float* b_fgl = (const float*)d_in[2];   // [4, 512]
    const float* W_fc  = (const float*)d_in[3];   // [2048, 10]
    const float* b_fc  = (const float*)d_in[4];   // [10]
    const int*   seg   = (const int*)d_in[5];     // [65536]
    float* out = (float*)d_out;                   // [512, 10]

    cudaFuncSetAttribute(fused_main_k,
                         cudaFuncAttributeMaxDynamicSharedMemorySize, SMEM_TOTAL);

    fused_main_k<<<GRIDM, 512, SMEM_TOTAL>>>(x, seg, W_fgl, b_fgl, W_fc, b_fc, out);
    (void)in_sizes; (void)n_in; (void)out_size;
}

// round 14
// speedup vs baseline: 1.2407x; 1.2407x over previous
#include <cuda_runtime.h>
#include <cstdint>

// Problem constants
#define B_       512
#define P_       65536
#define NOUT_    512
#define COUT_    4
#define NCLS_    10

// Decomposition: grid 148 = 4 row-groups (128 rows) x 37 px-groups, 1 block/SM.
// R14: warp-private pipelines. Warp w owns px column [w*8, w*8+8) of every
// tile; it stages its own 128-row x 32B slice with its own cp.async groups and
// NEVER block-syncs in the main loop (R12/13 showed tile-synchronous barriers
// convoy all 512 threads on the slowest of 128 strided DRAM streams).
#define RGS      4
#define RROWS    128
#define PGS      37
#define GRIDM    (RGS * PGS)          // 148
#define TILE_P   128
#define TILES_RG 512
#define WPX      8                    // px per warp per tile
#define WPAD     12
#define DEPTH    2

#define XW_BYTES   (RROWS * 48)                       // 6144 per warp per buf (48B row stride)
#define XWALL      (16 * DEPTH * XW_BYTES)            // 196608
#define WSM_OFF    XWALL
#define WSM_BYTES  (NOUT_ * WPAD * 4)                 // 24576
#define SEGW_OFF   (WSM_OFF + WSM_BYTES)              // per-warp seg: [16][2][32B]
#define SEGW_BYTES (16 * DEPTH * 32)                  // 1024
#define BRED_OFF   (SEGW_OFF + SEGW_BYTES)
#define BRED_BYTES 704
#define SMEM_TOTAL (BRED_OFF + BRED_BYTES)            // 222912 <= 232448

// Scratch (allocation-free)
__device__ float g_partial[PGS * B_ * NCLS_];   // [37][512][10]
__device__ int   g_cnt[RGS];                    // arrival counters (reset by finalizer)

__device__ __forceinline__ uint32_t smem_u32(const void* p) {
    return (uint32_t)__cvta_generic_to_shared(p);
}
__device__ __forceinline__ void cp16(uint32_t smem, const void* gmem) {
    asm volatile("cp.async.cg.shared.global [%0], [%1], 16;" :: "r"(smem), "l"(gmem));
}
__device__ __forceinline__ unsigned long long packf2(float v) {
    unsigned long long r;
    asm("mov.b64 %0, {%1, %1};" : "=l"(r) : "f"(v));
    return r;
}
#define FMA2(acc, xv, wv) \
    asm("fma.rn.f32x2 %0, %1, %2, %0;" : "+l"(acc) : "l"(xv), "l"(wv))

// ---------------------------------------------------------------------------
__global__ void __launch_bounds__(512, 1)
fused_main_k(const float* __restrict__ x, const int* __restrict__ seg,
             const float* __restrict__ W_fgl, const float* __restrict__ b_fgl,
             const float* __restrict__ W_fc, const float* __restrict__ b_fc,
             float* __restrict__ out) {
    extern __shared__ __align__(16) char dynsmem[];
    float* wsm  = (float*)(dynsmem + WSM_OFF);       // [512*12]
    float* bred = (float*)(dynsmem + BRED_OFF);      // [16][10]
    float* bsm  = bred + 16 * NCLS_;                 // [10]

    const int t    = threadIdx.x;
    const int warp = t >> 5;
    const int lane = t & 31;
    const int g    = blockIdx.x / PGS;      // row-group (0..3)
    const int pg   = blockIdx.x % PGS;      // px-group  (0..36)
    const int tStart = (pg * TILES_RG) / PGS;
    const int nT     = ((pg + 1) * TILES_RG) / PGS - tStart;   // 13 or 14

    const float* xbase = x + (size_t)(g * RROWS) * P_;
    // warp-private buffers
    char* xwb0 = dynsmem + warp * DEPTH * XW_BYTES;
    const uint32_t xw_u0  = smem_u32(xwb0);
    const uint32_t seg_u0 = smem_u32(dynsmem + SEGW_OFF + warp * DEPTH * 32);

    // Stage tile ft's warp slice into buf ft&1 (per-warp, no cross-warp deps).
    auto stage = [&](int ft) {
        int buf  = ft & 1;
        int pOff = (tStart + ft) * TILE_P + warp * WPX;   // 32B-aligned
        uint32_t dst = xw_u0 + buf * XW_BYTES;
#pragma unroll
        for (int rs = 0; rs < 4; rs++) {
            int row = lane + rs * 32;
            const float* gsrc = xbase + (size_t)row * P_ + pOff;
            cp16(dst + row * 48,      gsrc);       // px 0..3
            cp16(dst + row * 48 + 16, gsrc + 4);   // px 4..7
        }
        if (lane < 2)
            cp16(seg_u0 + buf * 32 + lane * 16, seg + pOff + lane * 4);
    };

    // Prologue: stage tile 0, then build Weff + beff (overlapped with DMA).
    stage(0);
    asm volatile("cp.async.commit_group;");
    {
        int j = t;                              // 512 threads == 512 regions
        float w[NCLS_], locb[NCLS_];
#pragma unroll
        for (int k = 0; k < NCLS_; k++) { w[k] = 0.f; locb[k] = 0.f; }
#pragma unroll
        for (int c = 0; c < COUT_; c++) {
            int r = c * NOUT_ + j;
            float a  = W_fgl[r];
            float bb = b_fgl[r];
            const float* wf = W_fc + r * NCLS_;
#pragma unroll
            for (int k = 0; k < NCLS_; k++) {
                float wv = wf[k];
                w[k]    += a * wv;
                locb[k] += bb * wv;
            }
        }
#pragma unroll
        for (int k = 0; k < NCLS_; k++) wsm[j * WPAD + k] = w[k];
#pragma unroll
        for (int off = 16; off >= 1; off >>= 1)
#pragma unroll
            for (int k = 0; k < NCLS_; k++)
                locb[k] += __shfl_xor_sync(0xffffffffu, locb[k], off);
        if (lane == 0)
#pragma unroll
            for (int k = 0; k < NCLS_; k++) bred[warp * NCLS_ + k] = locb[k];
    }
    __syncthreads();   // wsm/bred visible to all warps (ONLY pre-loop barrier)

    unsigned long long acc[4][5];   // [row-set][class-pair] f32x2
#pragma unroll
    for (int rs = 0; rs < 4; rs++)
#pragma unroll
        for (int q = 0; q < 5; q++) acc[rs][q] = 0ull;

    auto compute = [&](int buf) {
        const char* xb = xwb0 + buf * XW_BYTES;
        const int4* sp = (const int4*)(dynsmem + SEGW_OFF + (warp * DEPTH + buf) * 32);
        int4 s0 = sp[0];                         // 8 seg ids (warp-uniform)
        int4 s1 = sp[1];
#pragma unroll
        for (int h = 0; h < 2; h++) {            // px quads
            float4 xr[4];
#pragma unroll
            for (int rs = 0; rs < 4; rs++)       // rows lane,+32,+64,+96
                xr[rs] = *(const float4*)(xb + (lane + rs * 32) * 48 + h * 16);
            int4 sid = h ? s1 : s0;
#pragma unroll
            for (int j = 0; j < 4; j++) {
                int id = (j == 0) ? sid.x : (j == 1) ? sid.y : (j == 2) ? sid.z : sid.w;
                const unsigned long long* wrow =
                    (const unsigned long long*)&wsm[id * WPAD];
                ulonglong2 wab = *(const ulonglong2*)(wrow);      // k0..3 (broadcast)
                ulonglong2 wcd = *(const ulonglong2*)(wrow + 2);  // k4..7
                unsigned long long we = wrow[4];                   // k8..9
#pragma unroll
                for (int rs = 0; rs < 4; rs++) {
                    float xv = (j == 0) ? xr[rs].x : (j == 1) ? xr[rs].y
                             : (j == 2) ? xr[rs].z : xr[rs].w;
                    unsigned long long xp = packf2(xv);
                    FMA2(acc[rs][0], xp, wab.x);
                    FMA2(acc[rs][1], xp, wab.y);
                    FMA2(acc[rs][2], xp, wcd.x);
                    FMA2(acc[rs][3], xp, wcd.y);
                    FMA2(acc[rs][4], xp, we);
                }
            }
        }
    };

    // Main loop: per-warp double-buffered pipeline, NO block barriers.
#pragma unroll 1
    for (int ft = 0; ft < nT; ft++) {
        if (ft + 1 < nT) {
            stage(ft + 1);                                  // buf (ft+1)&1: warp's
            asm volatile("cp.async.commit_group;");         //  own prior compute done
            asm volatile("cp.async.wait_group 1;");         // tile ft arrived
        } else {
            asm volatile("cp.async.wait_group 0;");
        }
        compute(ft & 1);
    }
    __syncthreads();   // all warps done; x region reusable as reduction space

    // Epilogue: reduce 16 warps' partials -> one block partial (fixed order).
    float* red = (float*)dynsmem;                          // 10240 floats used
#pragma unroll
    for (int rs = 0; rs < 4; rs++) {
        int row = lane + rs * 32;
        if (warp < 8) {
#pragma unroll
            for (int q = 0; q < 5; q++) {
                float lo, hi;
                asm("mov.b64 {%0,%1}, %2;" : "=f"(lo), "=f"(hi) : "l"(acc[rs][q]));
                red[(warp * RROWS + row) * NCLS_ + 2 * q]     = lo;
                red[(warp * RROWS + row) * NCLS_ + 2 * q + 1] = hi;
            }
        }
    }
    __syncthreads();
    if (warp >= 8) {
#pragma unroll
        for (int rs = 0; rs < 4; rs++) {
            int row = lane + rs * 32;
            float* dst = &red[((warp - 8) * RROWS + row) * NCLS_];
#pragma unroll
            for (int q = 0; q < 5; q++) {
                float lo, hi;
                asm("mov.b64 {%0,%1}, %2;" : "=f"(lo), "=f"(hi) : "l"(acc[rs][q]));
                dst[2 * q]     += lo;
                dst[2 * q + 1] += hi;
            }
        }
    }
    __syncthreads();
#pragma unroll
    for (int off = 4; off >= 1; off >>= 1) {
        for (int i = t; i < off * RROWS * NCLS_; i += 512) {
            int slot = i / (RROWS * NCLS_);
            int rem  = i - slot * (RROWS * NCLS_);
            red[slot * RROWS * NCLS_ + rem] += red[(slot + off) * RROWS * NCLS_ + rem];
        }
        __syncthreads();
    }
    if (t < NCLS_) {            // bsm: 16 warp beff partials + b_fc (fixed order)
        float a0 = 0.f, a1 = 0.f;
#pragma unroll
        for (int i = 0; i < 16; i += 2) {
            a0 += bred[i * NCLS_ + t];
            a1 += bred[(i + 1) * NCLS_ + t];
        }
        bsm[t] = b_fc[t] + a0 + a1;
    }
    for (int i = t; i < RROWS * NCLS_; i += 512) {   // 1280 entries
        g_partial[((size_t)pg * B_ + g * RROWS) * NCLS_ + i] = red[i];
    }
    __syncthreads();

    // Last block of this row-group finalizes (threadFenceReduction pattern).
    __shared__ int is_last;
    if (t == 0) {
        __threadfence();
        int old = atomicAdd(&g_cnt[g], 1);
        is_last = (old == PGS - 1);
    }
    __syncthreads();
    if (is_last) {
        __threadfence();   // acquire all 37 partials
        for (int i = t; i < RROWS * NCLS_; i += 512) {
            int n = g * RROWS + i / NCLS_;
            int k = i % NCLS_;
            float sum = bsm[k];
#pragma unroll
            for (int s = 0; s < PGS; s++)      // fixed order: deterministic
                sum += g_partial[((size_t)s * B_ + n) * NCLS_ + k];
            out[n * NCLS_ + k] = sum;
        }
        __syncthreads();
        if (t == 0) g_cnt[g] = 0;              // reset for next (graph) launch
    }
}

// ---------------------------------------------------------------------------
extern "C" void kernel_launch(void* const* d_in, const int* in_sizes, int n_in,
                              void* d_out, int out_size) {
    const float* x     = (const float*)d_in[0];   // [512, 65536]
    const float* W_fgl = (const float*)d_in[1];   // [4, 512]
    const float* b_fgl = (const float*)d_in[2];   // [4, 512]
    const float* W_fc  = (const float*)d_in[3];   // [2048, 10]
    const float* b_fc  = (const float*)d_in[4];   // [10]
    const int*   seg   = (const int*)d_in[5];     // [65536]
    float* out = (float*)d_out;                   // [512, 10]

    cudaFuncSetAttribute(fused_main_k,
                         cudaFuncAttributeMaxDynamicSharedMemorySize, SMEM_TOTAL);

    fused_main_k<<<GRIDM, 512, SMEM_TOTAL>>>(x, seg, W_fgl, b_fgl, W_fc, b_fc, out);
    (void)in_sizes; (void)n_in; (void)out_size;
}

// round 15
// speedup vs baseline: 1.3232x; 1.0665x over previous
#include <cuda_runtime.h>
#include <cstdint>

// Problem constants
#define B_    512
#define P_    65536
#define NOUT_ 512
#define COUT_ 4
#define NCLS_ 10

// R15: stream-locality layout. 512 units = 128 quads (4 rows) x 4 px-quarters
// (16384 px). Block b owns contiguous units [b*512/148,(b+1)*512/148) -> 3..4.
// x is read as a few LONG sequential per-row streams via coalesced LDG.128
// straight to registers (no smem staging). Weights gathered per-px from a
// 20KB smem Weff table (WPAD=10 floats = 40B rows, LDS.64 x5).
#define GRIDM 148
#define QUADS 128
#define UNITS 512
#define QPX   16384
#define WPAD  10

// Scratch (allocation-free)
__device__ float g_partial[QUADS * 4 * 4 * NCLS_];  // [quad][slot][4rows][10], 80KB
__device__ int   g_qcnt[QUADS];                     // per-quad unit counters

__device__ __forceinline__ uint32_t smem_u32(const void* p) {
    return (uint32_t)__cvta_generic_to_shared(p);
}
__device__ __forceinline__ unsigned long long packf2(float v) {
    unsigned long long r;
    asm("mov.b64 %0, {%1, %1};" : "=l"(r) : "f"(v));
    return r;
}
__device__ __forceinline__ void lds64(unsigned long long& v, uint32_t a) {
    asm volatile("ld.shared.b64 %0, [%1];" : "=l"(v) : "r"(a));
}
__device__ __forceinline__ unsigned long long addf2(unsigned long long a,
                                                    unsigned long long b) {
    unsigned long long r;
    asm("add.rn.f32x2 %0, %1, %2;" : "=l"(r) : "l"(a), "l"(b));
    return r;
}
#define FMA2(acc, xv, wv) \
    asm("fma.rn.f32x2 %0, %1, %2, %0;" : "+l"(acc) : "l"(xv), "l"(wv))

struct Stage { int4 sid; float4 xr[4]; };

// ---------------------------------------------------------------------------
__global__ void __launch_bounds__(512, 1)
fused_main_k(const float* __restrict__ x, const int* __restrict__ seg,
             const float* __restrict__ W_fgl, const float* __restrict__ b_fgl,
             const float* __restrict__ W_fc, const float* __restrict__ b_fc,
             float* __restrict__ out) {
    __shared__ float wsm[NOUT_ * WPAD];        // 20KB Weff table (gather target)
    __shared__ float red[16][4 * NCLS_];       // per-warp flush partials
    __shared__ float bred[16][NCLS_];
    __shared__ float bsm[NCLS_];
    __shared__ int   finQ;

    const int t    = threadIdx.x;
    const int warp = t >> 5;
    const int lane = t & 31;
    const int b    = blockIdx.x;
    const int uS   = (b * UNITS) / GRIDM;
    const int uE   = ((b + 1) * UNITS) / GRIDM;
    const uint32_t wsm_u = smem_u32(wsm);

    // Prologue: build Weff (smem) + beff (shfl tree) from W_fgl/b_fgl/W_fc.
    {
        int j = t;                              // 512 threads == 512 regions
        float w[NCLS_], locb[NCLS_];
#pragma unroll
        for (int k = 0; k < NCLS_; k++) { w[k] = 0.f; locb[k] = 0.f; }
#pragma unroll
        for (int c = 0; c < COUT_; c++) {
            int r = c * NOUT_ + j;
            float a  = W_fgl[r];
            float bb = b_fgl[r];
            const float* wf = W_fc + r * NCLS_;
#pragma unroll
            for (int k = 0; k < NCLS_; k++) {
                float wv = wf[k];
                w[k]    += a * wv;
                locb[k] += bb * wv;
            }
        }
#pragma unroll
        for (int k = 0; k < NCLS_; k++) wsm[j * WPAD + k] = w[k];
#pragma unroll
        for (int off = 16; off >= 1; off >>= 1)
#pragma unroll
            for (int k = 0; k < NCLS_; k++)
                locb[k] += __shfl_xor_sync(0xffffffffu, locb[k], off);
        if (lane == 0)
#pragma unroll
            for (int k = 0; k < NCLS_; k++) bred[warp][k] = locb[k];
    }
    __syncthreads();
    if (t < NCLS_) {                           // fixed order: deterministic
        float a0 = 0.f, a1 = 0.f;
#pragma unroll
        for (int i = 0; i < 16; i += 2) { a0 += bred[i][t]; a1 += bred[i + 1][t]; }
        bsm[t] = b_fc[t] + a0 + a1;
    }
    // bsm read only after later __syncthreads (in flush) — safe.

    unsigned long long acc[4][5];              // [row][class-pair] f32x2

    int u = uS;
#pragma unroll 1
    while (u < uE) {
        const int quad = u >> 2;
        const int qa   = u & 3;
        const int segE = min(uE, (quad + 1) * 4);
        const int qb   = segE - quad * 4;      // quarters [qa, qb) this pass

#pragma unroll
        for (int rr = 0; rr < 4; rr++)
#pragma unroll
            for (int q = 0; q < 5; q++) acc[rr][q] = 0ull;

        const float* xq = x + (size_t)(quad * 4) * P_;
        const int base  = qa * QPX + warp * 128 + lane * 4;
        const int nIt   = (qb - qa) * (QPX / 2048);   // 8..32, even

        auto load = [&](Stage& S, int p) {
            S.sid = *(const int4*)(seg + p);          // L2-hot after 1st block
#pragma unroll
            for (int rr = 0; rr < 4; rr++)            // 4 sequential row streams
                S.xr[rr] = *(const float4*)(xq + (size_t)rr * P_ + p);
        };
        auto process = [&](Stage& S) {
#pragma unroll
            for (int j = 0; j < 4; j++) {
                int id = (j == 0) ? S.sid.x : (j == 1) ? S.sid.y
                       : (j == 2) ? S.sid.z : S.sid.w;
                uint32_t wa = wsm_u + (uint32_t)id * (WPAD * 4);
                unsigned long long w0, w1, w2, w3, w4;   // 40B gather
                lds64(w0, wa);      lds64(w1, wa + 8);  lds64(w2, wa + 16);
                lds64(w3, wa + 24); lds64(w4, wa + 32);
#pragma unroll
                for (int rr = 0; rr < 4; rr++) {
                    float xv = (j == 0) ? S.xr[rr].x : (j == 1) ? S.xr[rr].y
                             : (j == 2) ? S.xr[rr].z : S.xr[rr].w;
                    unsigned long long xp = packf2(xv);
                    FMA2(acc[rr][0], xp, w0);
                    FMA2(acc[rr][1], xp, w1);
                    FMA2(acc[rr][2], xp, w2);
                    FMA2(acc[rr][3], xp, w3);
                    FMA2(acc[rr][4], xp, w4);
                }
            }
        };

        Stage S0, S1;
        load(S0, base);
#pragma unroll 1
        for (int it = 0; it < nIt; it += 2) {          // nIt even
            load(S1, base + (it + 1) * 2048);
            process(S0);
            if (it + 2 < nIt) load(S0, base + (it + 2) * 2048);
            process(S1);
        }

        // ---- flush segment [qa, qb) of this quad ----
        // warp butterfly reduce (order identical on all lanes: deterministic)
#pragma unroll
        for (int rr = 0; rr < 4; rr++)
#pragma unroll
            for (int q = 0; q < 5; q++) {
                unsigned long long v = acc[rr][q];
#pragma unroll
                for (int off = 16; off >= 1; off >>= 1)
                    v = addf2(v, __shfl_xor_sync(0xffffffffu, v, off));
                acc[rr][q] = v;
            }
        if (lane == 0) {
#pragma unroll
            for (int rr = 0; rr < 4; rr++)
#pragma unroll
                for (int q = 0; q < 5; q++) {
                    float lo, hi;
                    asm("mov.b64 {%0,%1}, %2;" : "=f"(lo), "=f"(hi) : "l"(acc[rr][q]));
                    red[warp][rr * NCLS_ + 2 * q]     = lo;
                    red[warp][rr * NCLS_ + 2 * q + 1] = hi;
                }
        }
        __syncthreads();
        if (t < 4 * NCLS_) {
            float s = 0.f;
#pragma unroll
            for (int w = 0; w < 16; w++) s += red[w][t];   // fixed order
            g_partial[(quad * 4 + qa) * (4 * NCLS_) + t] = s;
            for (int sl = qa + 1; sl < qb; sl++)           // covered slots -> 0
                g_partial[(quad * 4 + sl) * (4 * NCLS_) + t] = 0.f;
        }
        __threadfence();          // release partials (all threads fence)
        __syncthreads();
        if (t == 0) {
            int add = qb - qa;
            int old = atomicAdd(&g_qcnt[quad], add);
            finQ = (old + add == 4) ? quad : -1;
        }
        __syncthreads();
        if (finQ >= 0) {          // last unit of this quad: finalize 4 rows
            __threadfence();      // acquire all 4 slots
            if (t < 4 * NCLS_) {
                float s = bsm[t % NCLS_];
#pragma unroll
                for (int sl = 0; sl < 4; sl++)             // fixed order
                    s += g_partial[(finQ * 4 + sl) * (4 * NCLS_) + t];
                out[finQ * (4 * NCLS_) + t] = s;
            }
            __syncthreads();
            if (t == 0) g_qcnt[finQ] = 0;  // reset for next (graph) launch
        }
        u = segE;
    }
}

// ---------------------------------------------------------------------------
extern "C" void kernel_launch(void* const* d_in, const int* in_sizes, int n_in,
                              void* d_out, int out_size) {
    const float* x     = (const float*)d_in[0];   // [512, 65536]
    const float* W_fgl = (const float*)d_in[1];   // [4, 512]
    const float* b_fgl = (const float*)d_in[2];   // [4, 512]
    const float* W_fc  = (const float*)d_in[3];   // [2048, 10]
    const float* b_fc  = (const float*)d_in[4];   // [10]
    const int*   seg   = (const int*)d_in[5];     // [65536]
    float* out = (float*)d_out;                   // [512, 10]

    fused_main_k<<<GRIDM, 512>>>(x, seg, W_fgl, b_fgl, W_fc, b_fc, out);
    (void)in_sizes; (void)n_in; (void)out_size;
}